// round 3
// baseline (speedup 1.0000x reference)
#include <cuda_runtime.h>
#include <float.h>

#define NA 8400
#define NB 64
#define NC 32
#define MAXD 100
#define CONF_T 0.25f
#define IOU_T 0.45f

#define NT1 256
#define NJ (NA / 4)          // 2100 float4-columns per image

#define NT2 1024
#define NW 32
#define SEG_CAP 288

// scratch (static device globals — allowed)
__device__ float4        g_box[NB * NA];   // corner boxes (y1,x1,y2,x2)
__device__ float         g_sc [NB * NA];   // conf-masked best score (-1 if < CONF)
__device__ unsigned char g_cls[NB * NA];   // best class

// dynamic smem for kernel 2: float4 box[NA] | float sc[NA] | u16 seg[2][NW*SEG_CAP] | u8 cls[NA]
#define SM_BOX_B (NA * 16)
#define SM_SC_B  (NA * 4)
#define SM_SEG_B (2 * NW * SEG_CAP * 2)
#define SM_CLS_B (NA)
#define SMEM2_BYTES (SM_BOX_B + SM_SC_B + SM_SEG_B + SM_CLS_B)

// ---------------- Kernel 1: decode (full-chip, streaming) ----------------
__global__ __launch_bounds__(NT1)
void decode_kernel(const float* __restrict__ in)
{
    const int j = blockIdx.x * NT1 + threadIdx.x;   // float4-column
    const int b = blockIdx.y;
    if (j >= NJ) return;
    const float* base = in + (size_t)b * (4 + NC) * NA;

    const float4 xc = ((const float4*)(base + 0 * NA))[j];
    const float4 yc = ((const float4*)(base + 1 * NA))[j];
    const float4 ww = ((const float4*)(base + 2 * NA))[j];
    const float4 hh = ((const float4*)(base + 3 * NA))[j];

    float4 best = make_float4(-FLT_MAX, -FLT_MAX, -FLT_MAX, -FLT_MAX);
    int4   cls  = make_int4(0, 0, 0, 0);
    #pragma unroll
    for (int k = 0; k < NC; ++k) {
        float4 v = ((const float4*)(base + (4 + k) * NA))[j];
        if (v.x > best.x) { best.x = v.x; cls.x = k; }   // strict > => first max
        if (v.y > best.y) { best.y = v.y; cls.y = k; }
        if (v.z > best.z) { best.z = v.z; cls.z = k; }
        if (v.w > best.w) { best.w = v.w; cls.w = k; }
    }

    const int a0 = 4 * j;
    float4* ob = g_box + (size_t)b * NA + a0;
    {
        float h2, w2;
        h2 = hh.x * 0.5f; w2 = ww.x * 0.5f;
        ob[0] = make_float4(fminf(fmaxf(yc.x - h2, 0.f), 1.f), fminf(fmaxf(xc.x - w2, 0.f), 1.f),
                            fminf(fmaxf(yc.x + h2, 0.f), 1.f), fminf(fmaxf(xc.x + w2, 0.f), 1.f));
        h2 = hh.y * 0.5f; w2 = ww.y * 0.5f;
        ob[1] = make_float4(fminf(fmaxf(yc.y - h2, 0.f), 1.f), fminf(fmaxf(xc.y - w2, 0.f), 1.f),
                            fminf(fmaxf(yc.y + h2, 0.f), 1.f), fminf(fmaxf(xc.y + w2, 0.f), 1.f));
        h2 = hh.z * 0.5f; w2 = ww.z * 0.5f;
        ob[2] = make_float4(fminf(fmaxf(yc.z - h2, 0.f), 1.f), fminf(fmaxf(xc.z - w2, 0.f), 1.f),
                            fminf(fmaxf(yc.z + h2, 0.f), 1.f), fminf(fmaxf(xc.z + w2, 0.f), 1.f));
        h2 = hh.w * 0.5f; w2 = ww.w * 0.5f;
        ob[3] = make_float4(fminf(fmaxf(yc.w - h2, 0.f), 1.f), fminf(fmaxf(xc.w - w2, 0.f), 1.f),
                            fminf(fmaxf(yc.w + h2, 0.f), 1.f), fminf(fmaxf(xc.w + w2, 0.f), 1.f));
    }
    float4 sc;
    sc.x = (best.x >= CONF_T) ? best.x : -1.0f;
    sc.y = (best.y >= CONF_T) ? best.y : -1.0f;
    sc.z = (best.z >= CONF_T) ? best.z : -1.0f;
    sc.w = (best.w >= CONF_T) ? best.w : -1.0f;
    *(float4*)(g_sc + (size_t)b * NA + a0) = sc;
    uchar4 c4 = make_uchar4((unsigned char)cls.x, (unsigned char)cls.y,
                            (unsigned char)cls.z, (unsigned char)cls.w);
    *(uchar4*)(g_cls + (size_t)b * NA + a0) = c4;
}

// ---------------- Kernel 2: NMS (one CTA per image) ----------------
__global__ __launch_bounds__(NT2, 1)
void nms_kernel(float* __restrict__ out)
{
    extern __shared__ unsigned char smem_raw[];
    float4*         s_box = (float4*)smem_raw;
    float*          s_sc  = (float*)(smem_raw + SM_BOX_B);
    unsigned short* s_seg = (unsigned short*)(smem_raw + SM_BOX_B + SM_SC_B);
    unsigned char*  s_cls = (unsigned char*)(smem_raw + SM_BOX_B + SM_SC_B + SM_SEG_B);

    __shared__ float rv[2][NW];
    __shared__ int   ri[2][NW];

    const int b    = blockIdx.x;
    const int tid  = threadIdx.x;
    const int lane = tid & 31;
    const int w    = tid >> 5;
    const unsigned lt_mask = (1u << lane) - 1u;

    float* out_boxes = out;                          // [NB, MAXD, 4]
    float* out_cls   = out + (size_t)NB * MAXD * 4;  // [NB, MAXD]
    float* out_scr   = out_cls + (size_t)NB * MAXD;  // [NB, MAXD]
    float* out_num   = out_scr + (size_t)NB * MAXD;  // [NB]

    int cur  = 0;
    int nseg = 0;
    float bv = -FLT_MAX;
    int   bi = 0x7fffffff;

    // load scratch into SMEM + build per-warp live segments + seed first argmax
    #pragma unroll
    for (int t = 0; t < (NA + NT2 - 1) / NT2; ++t) {
        int a  = tid + t * NT2;
        bool va = (a < NA);
        float sc = -1.0f;
        if (va) {
            s_box[a] = g_box[(size_t)b * NA + a];
            sc       = g_sc[(size_t)b * NA + a];
            s_sc[a]  = sc;
            s_cls[a] = g_cls[(size_t)b * NA + a];
        }
        bool keep = va && (sc > 0.0f);
        unsigned m = __ballot_sync(0xffffffffu, keep);
        if (keep) {
            s_seg[cur * (NW * SEG_CAP) + w * SEG_CAP + nseg + __popc(m & lt_mask)] =
                (unsigned short)a;
            if (sc > bv) { bv = sc; bi = a; }   // per-lane indices ascend with t
        }
        nseg += __popc(m);
    }
    __syncthreads();

    for (int it = 0; ; ++it) {
        const int par = it & 1;
        // warp-level butterfly argmax (min-index tie-break)
        #pragma unroll
        for (int off = 16; off > 0; off >>= 1) {
            float ov = __shfl_xor_sync(0xffffffffu, bv, off);
            int   oi = __shfl_xor_sync(0xffffffffu, bi, off);
            if (ov > bv || (ov == bv && oi < bi)) { bv = ov; bi = oi; }
        }
        if (lane == 0) { rv[par][w] = bv; ri[par][w] = bi; }
        __syncthreads();   // the only barrier per iteration
        // every warp redundantly reduces the 32 candidates -> identical pick everywhere
        float pv = rv[par][lane];
        int   pi = ri[par][lane];
        #pragma unroll
        for (int off = 16; off > 0; off >>= 1) {
            float ov = __shfl_xor_sync(0xffffffffu, pv, off);
            int   oi = __shfl_xor_sync(0xffffffffu, pi, off);
            if (ov > pv || (ov == pv && oi < pi)) { pv = ov; pi = oi; }
        }

        if (pv <= 0.0f) {   // live set empty: remaining slots are exact zeros
            for (int i = it * 4 + tid; i < MAXD * 4; i += NT2)
                out_boxes[(size_t)b * MAXD * 4 + i] = 0.0f;
            for (int i = it + tid; i < MAXD; i += NT2) {
                out_cls[(size_t)b * MAXD + i] = 0.0f;
                out_scr[(size_t)b * MAXD + i] = 0.0f;
            }
            if (tid == 0) out_num[b] = (float)it;
            return;
        }

        float4 pb = s_box[pi];   // uniform LDS broadcast
        if (tid == 0) {
            float* ob = out_boxes + ((size_t)b * MAXD + it) * 4;
            ob[0] = pb.x; ob[1] = pb.y; ob[2] = pb.z; ob[3] = pb.w;
            out_cls[(size_t)b * MAXD + it] = (float)s_cls[pi];
            out_scr[(size_t)b * MAXD + it] = pv;
        }
        if (it == MAXD - 1) {
            if (tid == 0) out_num[b] = (float)MAXD;
            return;
        }

        // fused suppress + compact + next-argmax over this warp's segment
        const float area_a = (pb.z - pb.x) * (pb.w - pb.y);
        bv = -FLT_MAX; bi = 0x7fffffff;
        const int nxt = cur ^ 1;
        int newn = 0;
        const int trips = (nseg + 31) >> 5;
        const unsigned short* __restrict__ src = s_seg + cur * (NW * SEG_CAP) + w * SEG_CAP;
        unsigned short*       __restrict__ dst = s_seg + nxt * (NW * SEG_CAP) + w * SEG_CAP;
        for (int t = 0; t < trips; ++t) {
            int  j  = lane + t * 32;
            bool vj = (j < nseg);
            int idx = vj ? (int)src[j] : 0;
            float4 bb = s_box[idx];
            float y1 = fmaxf(pb.x, bb.x);
            float x1 = fmaxf(pb.y, bb.y);
            float y2 = fminf(pb.z, bb.z);
            float x2 = fminf(pb.w, bb.w);
            float inter  = fmaxf(y2 - y1, 0.0f) * fmaxf(x2 - x1, 0.0f);
            float area_b = (bb.z - bb.x) * (bb.w - bb.y);
            float uni    = area_a + area_b - inter;
            float iou    = (uni > 0.0f) ? (inter / uni) : 0.0f;   // bitwise same as reference
            bool keep = vj && (idx != pi) && !(iou > IOU_T);
            unsigned m = __ballot_sync(0xffffffffu, keep);
            if (keep) {
                dst[newn + __popc(m & lt_mask)] = (unsigned short)idx;
                float sc = s_sc[idx];
                if (sc > bv || (sc == bv && idx < bi)) { bv = sc; bi = idx; }
            }
            newn += __popc(m);
        }
        nseg = newn;
        cur  = nxt;
        // no extra barrier: seg buffers warp-private; rv/ri double-buffered by parity
    }
}

extern "C" void kernel_launch(void* const* d_in, const int* in_sizes, int n_in,
                              void* d_out, int out_size)
{
    (void)in_sizes; (void)n_in; (void)out_size;
    const float* in = (const float*)d_in[0];
    float* out = (float*)d_out;

    dim3 g1((NJ + NT1 - 1) / NT1, NB);
    decode_kernel<<<g1, NT1>>>(in);

    cudaFuncSetAttribute(nms_kernel,
                         cudaFuncAttributeMaxDynamicSharedMemorySize,
                         (int)SMEM2_BYTES);
    nms_kernel<<<NB, NT2, SMEM2_BYTES>>>(out);
}